// round 15
// baseline (speedup 1.0000x reference)
#include <cuda_runtime.h>
#include <cuda_bf16.h>

// Problem shape (fixed by the dataset): B=64 segments, L=2048 tokens each,
// N=131072 tokens, D=512 features. Output = [B*D] means ++ [N] attn weights.
#define SEG_B   64
#define FEAT_D  512
#define D4      (FEAT_D / 4)     // 128 float4 lanes per row
#define SPLIT   16               // row-chunks per segment (128 rows each)
#define TPB     256              // 2 row-ways x 128 float4 lanes

__device__ __forceinline__ float4 ld_stream(const float4* p) { return __ldcs(p); }

// ---------------------------------------------------------------------------
// Single streaming kernel. Block = (segment b, row-chunk c): two row-ways of
// 128 threads each accumulate a contiguous 128x512 chunk (warp = 512B over
// 4 rows = 4 full lines, MLP 4 -- the proven fastest pattern). One smem fold
// merges the two ways, then 128 threads issue ONE float4 vector atomicAdd
// each (REDG.128) into the pre-zeroed out[b] row (order jitter ~1ulp,
// far below the 1e-3 tolerance).
// Prologue: parallel dtype-detect + shfl prefix scan of lengths (~100 cyc).
// ---------------------------------------------------------------------------
__global__ void __launch_bounds__(TPB)
mean_pool_stream(const float* __restrict__ x,
                 const void* __restrict__ lengths,
                 float* __restrict__ out,
                 float* __restrict__ attn,
                 long long n_total)
{
    const int b     = blockIdx.y;
    const int chunk = blockIdx.x;
    const int t     = threadIdx.x;
    const int way   = t >> 7;               // 0..1
    const int lane  = t & 127;              // float4 lane within row

    // ---- parallel lengths prologue (t < 64 active) ----
    __shared__ long long sh_incl[SEG_B];
    __shared__ int       sh_len[SEG_B];
    __shared__ long long sh_wsum[2];

    if (t < SEG_B) {
        const int wid = t >> 5;             // 0 or 1
        const int wl  = t & 31;
        // dtype detect: sum of int32 interpretation
        long long s32 = (long long)((const int*)lengths)[t];
        #pragma unroll
        for (int o = 16; o; o >>= 1)
            s32 += __shfl_xor_sync(0xffffffffu, s32, o);
        if (wl == 0) sh_wsum[wid] = s32;
    }
    __syncthreads();
    const bool is64 = (sh_wsum[0] + sh_wsum[1]) != n_total;

    if (t < SEG_B) {
        const int wl = t & 31;
        long long li = is64 ? ((const long long*)lengths)[t]
                            : (long long)((const int*)lengths)[t];
        long long v = li;
        #pragma unroll
        for (int o = 1; o < 32; o <<= 1) {
            long long u = __shfl_up_sync(0xffffffffu, v, o);
            if (wl >= o) v += u;
        }
        sh_incl[t] = v;                     // inclusive within warp
        sh_len[t]  = (int)li;
    }
    __syncthreads();
    if (t >= 32 && t < SEG_B) sh_incl[t] += sh_incl[31];
    __syncthreads();

    const int       len       = sh_len[b];
    const long long seg_start = sh_incl[b] - (long long)len;

    const int chunk_rows = (len + SPLIT - 1) / SPLIT;
    const int r0         = chunk * chunk_rows;
    const int rows       = max(min(chunk_rows, len - r0), 0);

    // ---- streaming accumulate: rows r = way, way+2, ... (stride 2 rows) ----
    const long long row2 = 2LL * D4;        // two rows in float4s
    const float4* p = reinterpret_cast<const float4*>(x)
                      + (seg_start + r0 + way) * (long long)D4 + lane;

    float4 acc = make_float4(0.f, 0.f, 0.f, 0.f);
    int r = way;
    for (; r + 6 < rows; r += 8, p += 4 * row2) {
        float4 a0 = ld_stream(&p[0 * row2]);
        float4 a1 = ld_stream(&p[1 * row2]);
        float4 a2 = ld_stream(&p[2 * row2]);
        float4 a3 = ld_stream(&p[3 * row2]);
        acc.x += (a0.x + a1.x) + (a2.x + a3.x);
        acc.y += (a0.y + a1.y) + (a2.y + a3.y);
        acc.z += (a0.z + a1.z) + (a2.z + a3.z);
        acc.w += (a0.w + a1.w) + (a2.w + a3.w);
    }
    for (; r < rows; r += 2, p += row2) {
        float4 a = ld_stream(&p[0]);
        acc.x += a.x; acc.y += a.y; acc.z += a.z; acc.w += a.w;
    }

    const float inv = 1.0f / (float)len;

    // attn weights for the rows this block owns (streaming stores)
    for (int rr = t; rr < rows; rr += TPB)
        __stcs(&attn[seg_start + r0 + rr], inv);

    // ---- fold the two row-ways, then ONE vector atomic per thread ----
    __shared__ float4 s_red[D4];
    if (way == 1) s_red[lane] = acc;
    __syncthreads();
    if (way == 0) {
        float4 o4 = s_red[lane];
        float4 v;
        v.x = (acc.x + o4.x) * inv;
        v.y = (acc.y + o4.y) * inv;
        v.z = (acc.z + o4.z) * inv;
        v.w = (acc.w + o4.w) * inv;
        // sm_90+ vector atomic: one REDG.128 instead of four scalar REDGs
        atomicAdd(reinterpret_cast<float4*>(out + b * FEAT_D + lane * 4), v);
    }
}

extern "C" void kernel_launch(void* const* d_in, const int* in_sizes, int n_in,
                              void* d_out, int out_size)
{
    const float* x       = (const float*)d_in[0];
    const void*  lengths = d_in[1];

    const long long n_total = (long long)in_sizes[0] / FEAT_D;

    float* out  = (float*)d_out;                 // [B, D] means first
    float* attn = out + SEG_B * FEAT_D;          // [N] attention weights

    // Zero only the mean region (atomics accumulate into it). Graph-legal.
    cudaMemsetAsync(out, 0, SEG_B * FEAT_D * sizeof(float), 0);

    dim3 grid(SPLIT, SEG_B);                     // 16 x 64 = 1024 CTAs, 1 wave
    mean_pool_stream<<<grid, TPB>>>(x, lengths, out, attn, n_total);
}

// round 16
// speedup vs baseline: 1.0143x; 1.0143x over previous
#include <cuda_runtime.h>
#include <cuda_bf16.h>

// Problem shape (fixed by the dataset): B=64 segments, L=2048 tokens each,
// N=131072 tokens, D=512 features. Output = [B*D] means ++ [N] attn weights.
#define SEG_B   64
#define FEAT_D  512
#define D4      (FEAT_D / 4)     // 128 float4 lanes per row
#define SPLIT   16               // row-chunks per segment (128 rows each)
#define TPB     256              // 2 row-ways x 128 float4 lanes

__device__ __forceinline__ float4 ld_stream(const float4* p) { return __ldcs(p); }

// ---------------------------------------------------------------------------
// Single streaming kernel. Block = (segment b, row-chunk c): two row-ways of
// 128 threads each accumulate a contiguous 128x512 chunk (warp = 512B over
// 4 rows = 4 full lines, MLP 4 -- the proven fastest pattern). One smem fold
// merges the two ways, then 128 threads issue 4 scalar fp atomicAdds each
// (REDG, spread addresses) into the pre-zeroed out[b] row (order jitter
// ~1ulp, far below the 1e-3 tolerance). Scalar atomics on purpose: the
// float4 vector atomic costs 8 extra registers (40 vs 32) and drops
// occupancy 8->6 CTAs/SM, a measured 4us regression.
// Prologue: parallel dtype-detect + shfl prefix scan of lengths (~100 cyc).
// ---------------------------------------------------------------------------
__global__ void __launch_bounds__(TPB, 8)
mean_pool_stream(const float* __restrict__ x,
                 const void* __restrict__ lengths,
                 float* __restrict__ out,
                 float* __restrict__ attn,
                 long long n_total)
{
    const int b     = blockIdx.y;
    const int chunk = blockIdx.x;
    const int t     = threadIdx.x;
    const int way   = t >> 7;               // 0..1
    const int lane  = t & 127;              // float4 lane within row

    // ---- parallel lengths prologue (t < 64 active) ----
    __shared__ long long sh_incl[SEG_B];
    __shared__ int       sh_len[SEG_B];
    __shared__ long long sh_wsum[2];

    if (t < SEG_B) {
        const int wid = t >> 5;             // 0 or 1
        const int wl  = t & 31;
        // dtype detect: sum of int32 interpretation
        long long s32 = (long long)((const int*)lengths)[t];
        #pragma unroll
        for (int o = 16; o; o >>= 1)
            s32 += __shfl_xor_sync(0xffffffffu, s32, o);
        if (wl == 0) sh_wsum[wid] = s32;
    }
    __syncthreads();
    const bool is64 = (sh_wsum[0] + sh_wsum[1]) != n_total;

    if (t < SEG_B) {
        const int wl = t & 31;
        long long li = is64 ? ((const long long*)lengths)[t]
                            : (long long)((const int*)lengths)[t];
        long long v = li;
        #pragma unroll
        for (int o = 1; o < 32; o <<= 1) {
            long long u = __shfl_up_sync(0xffffffffu, v, o);
            if (wl >= o) v += u;
        }
        sh_incl[t] = v;                     // inclusive within warp
        sh_len[t]  = (int)li;
    }
    __syncthreads();
    if (t >= 32 && t < SEG_B) sh_incl[t] += sh_incl[31];
    __syncthreads();

    const int       len       = sh_len[b];
    const long long seg_start = sh_incl[b] - (long long)len;

    const int chunk_rows = (len + SPLIT - 1) / SPLIT;
    const int r0         = chunk * chunk_rows;
    const int rows       = max(min(chunk_rows, len - r0), 0);

    // ---- streaming accumulate: rows r = way, way+2, ... (stride 2 rows) ----
    const long long row2 = 2LL * D4;        // two rows in float4s
    const float4* p = reinterpret_cast<const float4*>(x)
                      + (seg_start + r0 + way) * (long long)D4 + lane;

    float4 acc = make_float4(0.f, 0.f, 0.f, 0.f);
    int r = way;
    for (; r + 6 < rows; r += 8, p += 4 * row2) {
        float4 a0 = ld_stream(&p[0 * row2]);
        float4 a1 = ld_stream(&p[1 * row2]);
        float4 a2 = ld_stream(&p[2 * row2]);
        float4 a3 = ld_stream(&p[3 * row2]);
        acc.x += (a0.x + a1.x) + (a2.x + a3.x);
        acc.y += (a0.y + a1.y) + (a2.y + a3.y);
        acc.z += (a0.z + a1.z) + (a2.z + a3.z);
        acc.w += (a0.w + a1.w) + (a2.w + a3.w);
    }
    for (; r < rows; r += 2, p += row2) {
        float4 a = ld_stream(&p[0]);
        acc.x += a.x; acc.y += a.y; acc.z += a.z; acc.w += a.w;
    }

    const float inv = 1.0f / (float)len;

    // attn weights for the rows this block owns (streaming stores)
    for (int rr = t; rr < rows; rr += TPB)
        __stcs(&attn[seg_start + r0 + rr], inv);

    // ---- fold the two row-ways, then 4 scalar atomics per active thread ----
    __shared__ float4 s_red[D4];
    if (way == 1) s_red[lane] = acc;
    __syncthreads();
    if (way == 0) {
        float4 o4 = s_red[lane];
        acc.x = (acc.x + o4.x) * inv;
        acc.y = (acc.y + o4.y) * inv;
        acc.z = (acc.z + o4.z) * inv;
        acc.w = (acc.w + o4.w) * inv;
        float* o = out + b * FEAT_D + lane * 4;
        atomicAdd(o + 0, acc.x);
        atomicAdd(o + 1, acc.y);
        atomicAdd(o + 2, acc.z);
        atomicAdd(o + 3, acc.w);
    }
}

extern "C" void kernel_launch(void* const* d_in, const int* in_sizes, int n_in,
                              void* d_out, int out_size)
{
    const float* x       = (const float*)d_in[0];
    const void*  lengths = d_in[1];

    const long long n_total = (long long)in_sizes[0] / FEAT_D;

    float* out  = (float*)d_out;                 // [B, D] means first
    float* attn = out + SEG_B * FEAT_D;          // [N] attention weights

    // Zero only the mean region (atomics accumulate into it). Graph-legal.
    cudaMemsetAsync(out, 0, SEG_B * FEAT_D * sizeof(float), 0);

    dim3 grid(SPLIT, SEG_B);                     // 16 x 64 = 1024 CTAs, 1 wave
    mean_pool_stream<<<grid, TPB>>>(x, lengths, out, attn, n_total);
}

// round 17
// speedup vs baseline: 1.0956x; 1.0801x over previous
#include <cuda_runtime.h>
#include <cuda_bf16.h>

// Problem shape (fixed by the dataset): B=64 segments, L=2048 tokens each,
// N=131072 tokens, D=512 features. Output = [B*D] means ++ [N] attn weights.
#define SEG_B   64
#define FEAT_D  512
#define D4      (FEAT_D / 4)     // 128 float4 lanes per row
#define SPLIT   16               // row-chunks per segment (128 rows each)
#define TPB     256              // 2 row-ways x 128 float4 lanes

__device__ __forceinline__ float4 ld_stream(const float4* p) { return __ldcs(p); }

// ---------------------------------------------------------------------------
// Single streaming kernel (measured-best configuration, R14 = 44.6us kernel).
// Block = (segment b, row-chunk c): two row-ways of 128 threads each
// accumulate a contiguous 128x512 chunk (warp = 512B over 4 rows = 4 full
// lines, MLP 4). One smem fold merges the two ways, then 128 threads issue
// 4 scalar fp atomicAdds each (REDG, spread addresses) into the pre-zeroed
// out[b] row (order jitter ~1ulp, far below the 1e-3 tolerance).
// Deliberately NOT used (each measured as a regression):
//   - float4 vector atomicAdd: +8 regs -> occupancy 8->6 CTAs/SM (-4us)
//   - __stcs on attn stores: DRAM% 77->72 (-3.8us)
//   - __launch_bounds min-blocks hint, per-block scratch+fence reduction,
//     work-stealing, column-slab decomposition: all neutral or worse.
// Prologue: parallel dtype-detect + shfl prefix scan of lengths (~100 cyc);
// lengths may be int32 (JAX x64 disabled) or int64 as declared.
// ---------------------------------------------------------------------------
__global__ void __launch_bounds__(TPB)
mean_pool_stream(const float* __restrict__ x,
                 const void* __restrict__ lengths,
                 float* __restrict__ out,
                 float* __restrict__ attn,
                 long long n_total)
{
    const int b     = blockIdx.y;
    const int chunk = blockIdx.x;
    const int t     = threadIdx.x;
    const int way   = t >> 7;               // 0..1
    const int lane  = t & 127;              // float4 lane within row

    // ---- parallel lengths prologue (t < 64 active) ----
    __shared__ long long sh_incl[SEG_B];
    __shared__ int       sh_len[SEG_B];
    __shared__ long long sh_wsum[2];

    if (t < SEG_B) {
        const int wid = t >> 5;             // 0 or 1
        const int wl  = t & 31;
        // dtype detect: sum of int32 interpretation
        long long s32 = (long long)((const int*)lengths)[t];
        #pragma unroll
        for (int o = 16; o; o >>= 1)
            s32 += __shfl_xor_sync(0xffffffffu, s32, o);
        if (wl == 0) sh_wsum[wid] = s32;
    }
    __syncthreads();
    const bool is64 = (sh_wsum[0] + sh_wsum[1]) != n_total;

    if (t < SEG_B) {
        const int wl = t & 31;
        long long li = is64 ? ((const long long*)lengths)[t]
                            : (long long)((const int*)lengths)[t];
        long long v = li;
        #pragma unroll
        for (int o = 1; o < 32; o <<= 1) {
            long long u = __shfl_up_sync(0xffffffffu, v, o);
            if (wl >= o) v += u;
        }
        sh_incl[t] = v;                     // inclusive within warp
        sh_len[t]  = (int)li;
    }
    __syncthreads();
    if (t >= 32 && t < SEG_B) sh_incl[t] += sh_incl[31];
    __syncthreads();

    const int       len       = sh_len[b];
    const long long seg_start = sh_incl[b] - (long long)len;

    const int chunk_rows = (len + SPLIT - 1) / SPLIT;
    const int r0         = chunk * chunk_rows;
    const int rows       = max(min(chunk_rows, len - r0), 0);

    // ---- streaming accumulate: rows r = way, way+2, ... (stride 2 rows) ----
    const long long row2 = 2LL * D4;        // two rows in float4s
    const float4* p = reinterpret_cast<const float4*>(x)
                      + (seg_start + r0 + way) * (long long)D4 + lane;

    float4 acc = make_float4(0.f, 0.f, 0.f, 0.f);
    int r = way;
    for (; r + 6 < rows; r += 8, p += 4 * row2) {
        float4 a0 = ld_stream(&p[0 * row2]);
        float4 a1 = ld_stream(&p[1 * row2]);
        float4 a2 = ld_stream(&p[2 * row2]);
        float4 a3 = ld_stream(&p[3 * row2]);
        acc.x += (a0.x + a1.x) + (a2.x + a3.x);
        acc.y += (a0.y + a1.y) + (a2.y + a3.y);
        acc.z += (a0.z + a1.z) + (a2.z + a3.z);
        acc.w += (a0.w + a1.w) + (a2.w + a3.w);
    }
    for (; r < rows; r += 2, p += row2) {
        float4 a = ld_stream(&p[0]);
        acc.x += a.x; acc.y += a.y; acc.z += a.z; acc.w += a.w;
    }

    const float inv = 1.0f / (float)len;

    // attn weights for the rows this block owns (plain stores -- __stcs
    // measured as a regression here)
    for (int rr = t; rr < rows; rr += TPB)
        attn[seg_start + r0 + rr] = inv;

    // ---- fold the two row-ways, then 4 scalar atomics per active thread ----
    __shared__ float4 s_red[D4];
    if (way == 1) s_red[lane] = acc;
    __syncthreads();
    if (way == 0) {
        float4 o4 = s_red[lane];
        acc.x = (acc.x + o4.x) * inv;
        acc.y = (acc.y + o4.y) * inv;
        acc.z = (acc.z + o4.z) * inv;
        acc.w = (acc.w + o4.w) * inv;
        float* o = out + b * FEAT_D + lane * 4;
        atomicAdd(o + 0, acc.x);
        atomicAdd(o + 1, acc.y);
        atomicAdd(o + 2, acc.z);
        atomicAdd(o + 3, acc.w);
    }
}

extern "C" void kernel_launch(void* const* d_in, const int* in_sizes, int n_in,
                              void* d_out, int out_size)
{
    const float* x       = (const float*)d_in[0];
    const void*  lengths = d_in[1];

    const long long n_total = (long long)in_sizes[0] / FEAT_D;

    float* out  = (float*)d_out;                 // [B, D] means first
    float* attn = out + SEG_B * FEAT_D;          // [N] attention weights

    // Zero only the mean region (atomics accumulate into it). Graph-legal.
    cudaMemsetAsync(out, 0, SEG_B * FEAT_D * sizeof(float), 0);

    dim3 grid(SPLIT, SEG_B);                     // 16 x 64 = 1024 CTAs, 1 wave
    mean_pool_stream<<<grid, TPB>>>(x, lengths, out, attn, n_total);
}